// round 1
// baseline (speedup 1.0000x reference)
#include <cuda_runtime.h>
#include <stdint.h>

// Problem constants
#define BB 32
#define NN 1024
#define DD 768
#define D4 (DD/4)          // 192 float4 per row
#define KMASK 768          // masked tokens per row
#define NUNM  256          // unmasked tokens per row

// Output layout (float32 concat of the 5 reference outputs, flattened in order)
#define OFF_WITHMASK 0ull
#define OFF_UNMP   ((unsigned long long)BB*NN*DD)                       // 25165824
#define OFF_BOOL   (OFF_UNMP + (unsigned long long)BB*NUNM*DD)          // 31457280
#define OFF_MIDX   (OFF_BOOL + (unsigned long long)BB*NN*DD)            // 56623104
#define OFF_UIDX   (OFF_MIDX + (unsigned long long)BB*KMASK)            // 56647680

// Scratch: per-token info. -1 => masked; else rank among unmasked (0..255)
__device__ int g_info[BB * NN];

// ---------------------------------------------------------------------------
// Kernel 1: per-batch-row stable argsort of noise + mask/prefix-sum bookkeeping
// One block of 1024 threads per batch row. Bitonic sort on packed keys
// (float bits << 32 | index): positive uniform floats sort by bit pattern,
// index tiebreak == stable sort (matches jnp.argsort).
// ---------------------------------------------------------------------------
__global__ __launch_bounds__(1024, 1)
void mask_sort_kernel(const float* __restrict__ noise, float* __restrict__ out)
{
    __shared__ unsigned long long keys[NN];
    __shared__ int warp_sums[32];

    const int b = blockIdx.x;
    const int t = threadIdx.x;

    float v = noise[b * NN + t];
    keys[t] = ((unsigned long long)__float_as_uint(v) << 32) | (unsigned)t;
    __syncthreads();

    // Bitonic sort, ascending
    #pragma unroll 1
    for (int k = 2; k <= NN; k <<= 1) {
        #pragma unroll 1
        for (int j = k >> 1; j > 0; j >>= 1) {
            int ixj = t ^ j;
            if (ixj > t) {
                unsigned long long a = keys[t];
                unsigned long long c = keys[ixj];
                bool up = ((t & k) == 0);
                if ((a > c) == up) { keys[t] = c; keys[ixj] = a; }
            }
            __syncthreads();
        }
    }

    // perm[t] = original index of t-th smallest noise
    int perm = (int)(keys[t] & 0xFFFFFFFFu);
    int m = (perm < KMASK) ? 1 : 0;   // bool_mask at position t

    // Exclusive prefix sum of m across the 1024 threads (ballot + warp sums)
    const int lane = t & 31;
    const int warp = t >> 5;
    unsigned ballot = __ballot_sync(0xFFFFFFFFu, m);
    int before_in_warp = __popc(ballot & ((1u << lane) - 1u));
    if (lane == 0) warp_sums[warp] = __popc(ballot);
    __syncthreads();
    int warp_before = 0;
    #pragma unroll
    for (int w = 0; w < 32; ++w)
        warp_before += (w < warp) ? warp_sums[w] : 0;
    int t_before = warp_before + before_in_warp;   // # of Trues at positions < t

    // Emit index outputs (as float) + scratch info.
    // order = stable argsort(bool_mask): False positions first (ascending),
    // then True positions (ascending).
    float* masked_out = out + OFF_MIDX;
    float* unm_out    = out + OFF_UIDX;
    if (m) {
        masked_out[b * KMASK + t_before] = (float)t;
        g_info[b * NN + t] = -1;
    } else {
        int r = t - t_before;                      // rank among unmasked
        unm_out[b * NUNM + r] = (float)t;
        g_info[b * NN + t] = r;
    }
}

// ---------------------------------------------------------------------------
// Kernel 2: one block per token (B*N = 32768 blocks), 192 threads = float4/row.
// Writes with_mask row, bool_mask_expanded row, and (for unmasked tokens)
// scatters the loaded patch row into unmasked_patches_only. Patch is read
// ONLY for unmasked tokens (25 MB instead of 100 MB).
// ---------------------------------------------------------------------------
__global__ __launch_bounds__(192, 8)
void mask_scatter_kernel(const float* __restrict__ patch,
                         const float* __restrict__ mask_emb,
                         float* __restrict__ out)
{
    const int tok = blockIdx.x;          // b*N + j
    const int b   = tok >> 10;
    const int t   = threadIdx.x;         // float4 lane 0..191
    const int info = g_info[tok];

    float4* wm = reinterpret_cast<float4*>(out + OFF_WITHMASK) + (size_t)tok * D4;
    float4* be = reinterpret_cast<float4*>(out + OFF_BOOL)     + (size_t)tok * D4;

    const float bv = (info < 0) ? 1.0f : 0.0f;
    be[t] = make_float4(bv, bv, bv, bv);

    if (info < 0) {
        // masked: with_mask row = mask_emb (768 floats, L2-resident broadcast)
        float4 me = __ldg(reinterpret_cast<const float4*>(mask_emb) + t);
        wm[t] = me;
    } else {
        float4 p = __ldg(reinterpret_cast<const float4*>(patch) + (size_t)tok * D4 + t);
        wm[t] = p;
        float4* up = reinterpret_cast<float4*>(out + OFF_UNMP)
                   + ((size_t)b * NUNM + info) * D4;
        up[t] = p;
    }
}

extern "C" void kernel_launch(void* const* d_in, const int* in_sizes, int n_in,
                              void* d_out, int out_size)
{
    const float* patch    = (const float*)d_in[0];  // (B, N, D) f32
    const float* noise    = (const float*)d_in[1];  // (B, N)    f32
    const float* mask_emb = (const float*)d_in[2];  // (D,)      f32
    float* out = (float*)d_out;

    mask_sort_kernel<<<BB, 1024>>>(noise, out);
    mask_scatter_kernel<<<BB * NN, 192>>>(patch, mask_emb, out);
}